// round 12
// baseline (speedup 1.0000x reference)
#include <cuda_runtime.h>

#define N_NODES   1048576
#define N_GRAPHS  1024
#define F_X       128
#define F_U       128
#define F_CAT     256
#define HIDDEN    512
#define F_OUT     128

#define MLP_BLOCKS 256

// Scratch (allocation-free rule: __device__ globals)
__device__ float g_concat[N_GRAPHS * F_CAT];   // [1024,256] = x_agg || u
__device__ float g_h[N_GRAPHS * HIDDEN];       // [1024,512]

// Device-wide barrier state for the fused MLP kernel. Reset by seg_mean
// (earlier launch in the same stream) so every graph replay starts clean.
__device__ unsigned g_arrive;
__device__ volatile unsigned g_release;

// ---------------------------------------------------------------------------
// Warp-collective lower_bound on sorted int array: 32-ary search.
// ---------------------------------------------------------------------------
__device__ __forceinline__ int warp_lower_bound(const int* __restrict__ batch,
                                                int target, int lane) {
    int lo = 0, hi = N_NODES;              // answer in [lo, hi]
    while (hi - lo > 32) {
        int step = (hi - lo) >> 5;         // >= 1
        int pos  = lo + lane * step;
        int v    = __ldg(batch + pos);
        unsigned mask = __ballot_sync(0xffffffffu, v < target);
        if (mask == 0) {
            hi = lo + step;
        } else {
            int istar = 31 - __clz(mask);
            int nlo   = lo + istar * step;
            int nhi   = (istar < 31) ? (nlo + step) : hi;
            lo = nlo; hi = nhi;
        }
    }
    int pos = lo + lane;
    int v   = (pos < hi) ? __ldg(batch + pos) : 0x7fffffff;
    unsigned mask = __ballot_sync(0xffffffffu, (pos < hi) && (v < target));
    return lo + __popc(mask);
}

// ---------------------------------------------------------------------------
// 1) Segment mean of x -> g_concat[:,0:128]; u -> g_concat[:,128:256].
//    One block per graph, 256 threads, <=32 regs -> single wave (R8 config).
//    Block 0 thread 0 also resets the MLP barrier state for this replay.
// ---------------------------------------------------------------------------
__global__ void __launch_bounds__(256, 8) seg_mean_kernel(const float* __restrict__ x,
                                                          const float* __restrict__ u,
                                                          const int*   __restrict__ batch) {
    const int g    = blockIdx.x;
    const int tid  = threadIdx.x;
    const int lane = tid & 31;   // feature quad
    const int grp  = tid >> 5;   // row group 0..7

    if (g == 0 && tid == 0) {    // reset barrier for the following MLP kernel
        g_arrive  = 0u;
        g_release = 0u;
    }

    __shared__ int s_se[2];
    if (grp < 2) {               // warp 0 -> start, warp 1 -> end
        int r = warp_lower_bound(batch, g + grp, lane);
        if (lane == 0) s_se[grp] = r;
    }
    __syncthreads();
    const int start = s_se[0];
    const int end   = s_se[1];

    const float* xb = x + (size_t)lane * 4;

    float4 a0 = {0,0,0,0}, a1 = {0,0,0,0};
    int r = start + grp;
    for (; r + 8 < end; r += 16) {      // 2 loads in flight per thread
        float4 v0 = __ldcs((const float4*)(xb + (size_t)(r    ) * F_X));
        float4 v1 = __ldcs((const float4*)(xb + (size_t)(r + 8) * F_X));
        a0.x += v0.x; a0.y += v0.y; a0.z += v0.z; a0.w += v0.w;
        a1.x += v1.x; a1.y += v1.y; a1.z += v1.z; a1.w += v1.w;
    }
    if (r < end) {
        float4 v = __ldcs((const float4*)(xb + (size_t)r * F_X));
        a0.x += v.x; a0.y += v.y; a0.z += v.z; a0.w += v.w;
    }
    a0.x += a1.x; a0.y += a1.y; a0.z += a1.z; a0.w += a1.w;

    __shared__ float4 sm[8][32];
    sm[grp][lane] = a0;
    __syncthreads();
    #pragma unroll
    for (int s = 4; s > 0; s >>= 1) {
        if (grp < s) {
            float4 a = sm[grp][lane];
            float4 b = sm[grp + s][lane];
            a.x += b.x; a.y += b.y; a.z += b.z; a.w += b.w;
            sm[grp][lane] = a;
        }
        __syncthreads();
    }

    if (grp == 0) {
        int cnt = end - start;
        float inv = (cnt > 0) ? (1.0f / (float)cnt) : 0.0f;
        float4 a = sm[0][lane];
        a.x *= inv; a.y *= inv; a.z *= inv; a.w *= inv;
        *(float4*)(g_concat + (size_t)g * F_CAT + lane * 4) = a;
    } else if (grp == 1) {
        float4 v = *(const float4*)(u + (size_t)g * F_U + lane * 4);
        *(float4*)(g_concat + (size_t)g * F_CAT + F_X + lane * 4) = v;
    }
}

// ---------------------------------------------------------------------------
// 2) Fused MLP: one kernel, 256 blocks x 256 threads, all co-resident
//    (__launch_bounds__(256,2): capacity 296 >= 256 -> barrier is safe).
//    Phase 1: h = relu(concat @ W1 + b1), 64x32 tiles (grid 16x16).
//    Device barrier (atomic arrive + release flag).
//    Phase 2: out = h @ W2 + b2, 16x32 tiles (grid 64x4), 4-way in-block
//    split-K, deterministic fixed-order reduction.
// ---------------------------------------------------------------------------
__global__ void __launch_bounds__(256, 2) mlp_kernel(const float* __restrict__ W1,
                                                     const float* __restrict__ b1,
                                                     const float* __restrict__ W2,
                                                     const float* __restrict__ b2,
                                                     float* __restrict__ out) {
    const int bid = blockIdx.x;
    const int tid = threadIdx.x;

    // ---------------- Phase 1: GEMM1 64x32 tile ----------------
    {
        __shared__ float As[16][64 + 4];
        __shared__ float Bs[16][32];

        const int bm = (bid >> 4) * 64;       // 16 m-tiles
        const int bn = (bid & 15) * 32;       // 16 n-tiles
        const int tx = tid & 7;               // 8 cols of 4 (TN=4)
        const int ty = tid >> 3;              // 32 rows of 2 (TM=2)

        float acc[2][4] = {};

        for (int k0 = 0; k0 < F_CAT; k0 += 16) {
            {   // A tile 64x16 = 256 float4 (1 per thread), transposed store
                int row  = tid >> 2;
                int quad = tid & 3;
                float4 v = *(const float4*)(g_concat + (size_t)(bm + row) * F_CAT + k0 + quad * 4);
                As[quad * 4 + 0][row] = v.x;
                As[quad * 4 + 1][row] = v.y;
                As[quad * 4 + 2][row] = v.z;
                As[quad * 4 + 3][row] = v.w;
            }
            if (tid < 128) {  // B tile 16x32 = 128 float4
                int row  = tid >> 3;
                int quad = tid & 7;
                *(float4*)&Bs[row][quad * 4] =
                    *(const float4*)(W1 + (size_t)(k0 + row) * HIDDEN + bn + quad * 4);
            }
            __syncthreads();

            #pragma unroll
            for (int k = 0; k < 16; k++) {
                float2 a2 = *(const float2*)&As[k][ty * 2];
                float4 b4 = *(const float4*)&Bs[k][tx * 4];
                float b[4] = {b4.x, b4.y, b4.z, b4.w};
                #pragma unroll
                for (int j = 0; j < 4; j++) {
                    acc[0][j] = fmaf(a2.x, b[j], acc[0][j]);
                    acc[1][j] = fmaf(a2.y, b[j], acc[1][j]);
                }
            }
            __syncthreads();
        }

        float4 bv = *(const float4*)(b1 + bn + tx * 4);
        #pragma unroll
        for (int i = 0; i < 2; i++) {
            int row = bm + ty * 2 + i;
            float4 o;
            o.x = fmaxf(acc[i][0] + bv.x, 0.0f);
            o.y = fmaxf(acc[i][1] + bv.y, 0.0f);
            o.z = fmaxf(acc[i][2] + bv.z, 0.0f);
            o.w = fmaxf(acc[i][3] + bv.w, 0.0f);
            *(float4*)(g_h + (size_t)row * HIDDEN + bn + tx * 4) = o;
        }
    }

    // ---------------- Device-wide barrier ----------------
    __threadfence();                      // publish h
    __syncthreads();                      // whole block done with phase 1
    if (tid == 0) {
        unsigned t = atomicAdd(&g_arrive, 1u);
        if (t == (unsigned)(MLP_BLOCKS - 1)) g_release = 1u;
        while (g_release == 0u) { __nanosleep(32); }
    }
    __syncthreads();
    __threadfence();                      // acquire h from other blocks

    // ---------------- Phase 2: GEMM2 16x32 tile, 4-way split-K ----------------
    {
        __shared__ float As2[4][16][16 + 4];
        __shared__ float Bs2[4][16][32];
        __shared__ float red[3][16][32 + 4];

        const int bm = (bid >> 2) * 16;       // 64 m-tiles
        const int bn = (bid & 3) * 32;        // 4 n-tiles
        const int ks   = tid >> 6;            // k-slice 0..3
        const int ctid = tid & 63;
        const int tx   = ctid & 7;            // TN=4 -> 32 cols
        const int ty   = ctid >> 3;           // TM=2 -> 16 rows

        float acc[2][4] = {};

        const int kbeg = ks * (HIDDEN / 4);
        for (int k0 = kbeg; k0 < kbeg + HIDDEN / 4; k0 += 16) {
            {   // A slice-tile 16x16 = 64 float4 (1 per lane)
                int row  = ctid >> 2;
                int quad = ctid & 3;
                float4 v = *(const float4*)(g_h + (size_t)(bm + row) * HIDDEN + k0 + quad * 4);
                As2[ks][quad * 4 + 0][row] = v.x;
                As2[ks][quad * 4 + 1][row] = v.y;
                As2[ks][quad * 4 + 2][row] = v.z;
                As2[ks][quad * 4 + 3][row] = v.w;
            }
            #pragma unroll
            for (int i = 0; i < 2; i++) {  // B slice-tile 16x32 = 128 float4
                int idx  = ctid + 64 * i;
                int row  = idx >> 3;
                int quad = idx & 7;
                *(float4*)&Bs2[ks][row][quad * 4] =
                    *(const float4*)(W2 + (size_t)(k0 + row) * F_OUT + bn + quad * 4);
            }
            __syncthreads();

            #pragma unroll
            for (int k = 0; k < 16; k++) {
                float2 a2 = *(const float2*)&As2[ks][k][ty * 2];
                float4 b4 = *(const float4*)&Bs2[ks][k][tx * 4];
                float b[4] = {b4.x, b4.y, b4.z, b4.w};
                #pragma unroll
                for (int j = 0; j < 4; j++) {
                    acc[0][j] = fmaf(a2.x, b[j], acc[0][j]);
                    acc[1][j] = fmaf(a2.y, b[j], acc[1][j]);
                }
            }
            __syncthreads();
        }

        if (ks > 0) {
            #pragma unroll
            for (int i = 0; i < 2; i++)
                #pragma unroll
                for (int j = 0; j < 4; j++)
                    red[ks - 1][ty * 2 + i][tx * 4 + j] = acc[i][j];
        }
        __syncthreads();

        if (ks == 0) {
            float4 bv = *(const float4*)(b2 + bn + tx * 4);
            #pragma unroll
            for (int i = 0; i < 2; i++) {
                int row = bm + ty * 2 + i;
                float o[4];
                #pragma unroll
                for (int j = 0; j < 4; j++) {
                    float s = acc[i][j];
                    s += red[0][ty * 2 + i][tx * 4 + j];
                    s += red[1][ty * 2 + i][tx * 4 + j];
                    s += red[2][ty * 2 + i][tx * 4 + j];
                    o[j] = s;
                }
                float4 ov = {o[0] + bv.x, o[1] + bv.y, o[2] + bv.z, o[3] + bv.w};
                *(float4*)(out + (size_t)row * F_OUT + bn + tx * 4) = ov;
            }
        }
    }
}

// ---------------------------------------------------------------------------
// Launch. Inputs: x, edge_index, edge_attr, u, batch, W1, b1, W2, b2.
// edge_* unused; int64 inputs arrive as int32 on device.
// ---------------------------------------------------------------------------
extern "C" void kernel_launch(void* const* d_in, const int* in_sizes, int n_in,
                              void* d_out, int out_size) {
    const float* x     = (const float*)d_in[0];
    const float* u     = (const float*)d_in[3];
    const int*   batch = (const int*)d_in[4];
    const float* W1    = (const float*)d_in[5];
    const float* b1    = (const float*)d_in[6];
    const float* W2    = (const float*)d_in[7];
    const float* b2    = (const float*)d_in[8];
    float*       out   = (float*)d_out;

    // 1) segment mean + concat (also resets the MLP barrier), single wave
    seg_mean_kernel<<<N_GRAPHS, 256>>>(x, u, batch);

    // 2) fused MLP: GEMM1 + device barrier + GEMM2, one launch, 256 blocks
    mlp_kernel<<<MLP_BLOCKS, 256>>>(W1, b1, W2, b2, out);
}

// round 13
// speedup vs baseline: 1.0737x; 1.0737x over previous
#include <cuda_runtime.h>

#define N_NODES   1048576
#define N_GRAPHS  1024
#define F_X       128
#define F_U       128
#define F_CAT     256
#define HIDDEN    512
#define F_OUT     128

// Scratch (allocation-free rule: __device__ globals)
__device__ float g_concat[N_GRAPHS * F_CAT];   // [1024,256] = x_agg || u
__device__ float g_h[N_GRAPHS * HIDDEN];       // [1024,512]

// ---------------------------------------------------------------------------
// Warp-collective lower_bound on sorted int array: 32-ary search.
// ---------------------------------------------------------------------------
__device__ __forceinline__ int warp_lower_bound(const int* __restrict__ batch,
                                                int target, int lane) {
    int lo = 0, hi = N_NODES;              // answer in [lo, hi]
    while (hi - lo > 32) {
        int step = (hi - lo) >> 5;         // >= 1
        int pos  = lo + lane * step;
        int v    = __ldg(batch + pos);
        unsigned mask = __ballot_sync(0xffffffffu, v < target);
        if (mask == 0) {
            hi = lo + step;
        } else {
            int istar = 31 - __clz(mask);
            int nlo   = lo + istar * step;
            int nhi   = (istar < 31) ? (nlo + step) : hi;
            lo = nlo; hi = nhi;
        }
    }
    int pos = lo + lane;
    int v   = (pos < hi) ? __ldg(batch + pos) : 0x7fffffff;
    unsigned mask = __ballot_sync(0xffffffffu, (pos < hi) && (v < target));
    return lo + __popc(mask);
}

// ---------------------------------------------------------------------------
// 1) Segment mean of x -> g_concat[:,0:128]; u -> g_concat[:,128:256].
//    One block per graph, 256 threads; <=32 regs -> 8 blocks/SM -> all 1024
//    blocks in one wave. At the measured spr_max floor (~1.18x) -> done.
// ---------------------------------------------------------------------------
__global__ void __launch_bounds__(256, 8) seg_mean_kernel(const float* __restrict__ x,
                                                          const float* __restrict__ u,
                                                          const int*   __restrict__ batch) {
    const int g    = blockIdx.x;
    const int tid  = threadIdx.x;
    const int lane = tid & 31;   // feature quad
    const int grp  = tid >> 5;   // row group 0..7

    __shared__ int s_se[2];
    if (grp < 2) {               // warp 0 -> start, warp 1 -> end
        int r = warp_lower_bound(batch, g + grp, lane);
        if (lane == 0) s_se[grp] = r;
    }
    __syncthreads();
    const int start = s_se[0];
    const int end   = s_se[1];

    const float* xb = x + (size_t)lane * 4;

    float4 a0 = {0,0,0,0}, a1 = {0,0,0,0};
    int r = start + grp;
    for (; r + 8 < end; r += 16) {      // 2 loads in flight per thread
        float4 v0 = __ldcs((const float4*)(xb + (size_t)(r    ) * F_X));
        float4 v1 = __ldcs((const float4*)(xb + (size_t)(r + 8) * F_X));
        a0.x += v0.x; a0.y += v0.y; a0.z += v0.z; a0.w += v0.w;
        a1.x += v1.x; a1.y += v1.y; a1.z += v1.z; a1.w += v1.w;
    }
    if (r < end) {
        float4 v = __ldcs((const float4*)(xb + (size_t)r * F_X));
        a0.x += v.x; a0.y += v.y; a0.z += v.z; a0.w += v.w;
    }
    a0.x += a1.x; a0.y += a1.y; a0.z += a1.z; a0.w += a1.w;

    __shared__ float4 sm[8][32];
    sm[grp][lane] = a0;
    __syncthreads();
    #pragma unroll
    for (int s = 4; s > 0; s >>= 1) {
        if (grp < s) {
            float4 a = sm[grp][lane];
            float4 b = sm[grp + s][lane];
            a.x += b.x; a.y += b.y; a.z += b.z; a.w += b.w;
            sm[grp][lane] = a;
        }
        __syncthreads();
    }

    if (grp == 0) {
        int cnt = end - start;
        float inv = (cnt > 0) ? (1.0f / (float)cnt) : 0.0f;
        float4 a = sm[0][lane];
        a.x *= inv; a.y *= inv; a.z *= inv; a.w *= inv;
        *(float4*)(g_concat + (size_t)g * F_CAT + lane * 4) = a;
    } else if (grp == 1) {
        float4 v = *(const float4*)(u + (size_t)g * F_U + lane * 4);
        *(float4*)(g_concat + (size_t)g * F_CAT + F_X + lane * 4) = v;
    }
}

// ---------------------------------------------------------------------------
// 2) GEMM1 (fused bias+relu): h = relu(concat @ W1 + b1). 64x64 tiles,
//    BK=32 (half the barriers of BK=16), 256 threads, TM=TN=4,
//    register double-buffered inner loop.
// ---------------------------------------------------------------------------
template <int K, int N, int BM, int BN, int TM, int TN, int THREADS, bool RELU>
__global__ void __launch_bounds__(THREADS) gemm_kernel(const float* __restrict__ A,
                                                       const float* __restrict__ B,
                                                       const float* __restrict__ bias,
                                                       float* __restrict__ C) {
    constexpr int BK = 32;
    constexpr int TX = BN / TN;
    constexpr int TY = BM / TM;
    static_assert(TX * TY == THREADS, "bad tile");
    constexpr int AF4 = (BM * BK) / (4 * THREADS);   // 2 for 64x32/256
    constexpr int BF4 = (BK * BN) / (4 * THREADS);   // 2 for 32x64/256
    static_assert(AF4 >= 1 && BF4 >= 1, "tile too small");

    __shared__ float As[BK][BM + 4];
    __shared__ float Bs[BK][BN];

    const int bm  = blockIdx.y * BM;
    const int bn  = blockIdx.x * BN;
    const int tid = threadIdx.x;
    const int tx  = tid % TX;
    const int ty  = tid / TX;

    float acc[TM][TN] = {};

    for (int k0 = 0; k0 < K; k0 += BK) {
        #pragma unroll
        for (int i = 0; i < AF4; i++) {            // A tile BM x BK (quads/row = BK/4)
            int idx  = tid + THREADS * i;
            int row  = idx / (BK / 4);
            int quad = idx % (BK / 4);
            float4 v = *(const float4*)(A + (size_t)(bm + row) * K + k0 + quad * 4);
            As[quad * 4 + 0][row] = v.x;
            As[quad * 4 + 1][row] = v.y;
            As[quad * 4 + 2][row] = v.z;
            As[quad * 4 + 3][row] = v.w;
        }
        #pragma unroll
        for (int i = 0; i < BF4; i++) {            // B tile BK x BN
            int idx  = tid + THREADS * i;
            int row  = idx / (BN / 4);
            int quad = idx % (BN / 4);
            *(float4*)&Bs[row][quad * 4] =
                *(const float4*)(B + (size_t)(k0 + row) * N + bn + quad * 4);
        }
        __syncthreads();

        // register double-buffered k-loop: prefetch k+1 during k's FMAs
        float4 a4 = *(const float4*)&As[0][ty * TM];
        float4 b4 = *(const float4*)&Bs[0][tx * TN];
        #pragma unroll
        for (int k = 0; k < BK; k++) {
            float4 a4n = a4, b4n = b4;
            if (k + 1 < BK) {
                a4n = *(const float4*)&As[k + 1][ty * TM];
                b4n = *(const float4*)&Bs[k + 1][tx * TN];
            }
            float a[4] = {a4.x, a4.y, a4.z, a4.w};
            float b[4] = {b4.x, b4.y, b4.z, b4.w};
            #pragma unroll
            for (int i = 0; i < TM; i++)
                #pragma unroll
                for (int j = 0; j < TN; j++)
                    acc[i][j] = fmaf(a[i], b[j], acc[i][j]);
            a4 = a4n; b4 = b4n;
        }
        __syncthreads();
    }

    float4 bv = *(const float4*)(bias + bn + tx * TN);
    #pragma unroll
    for (int i = 0; i < TM; i++) {
        int row = bm + ty * TM + i;
        float4 o;
        o.x = acc[i][0] + bv.x;
        o.y = acc[i][1] + bv.y;
        o.z = acc[i][2] + bv.z;
        o.w = acc[i][3] + bv.w;
        if (RELU) {
            o.x = fmaxf(o.x, 0.0f); o.y = fmaxf(o.y, 0.0f);
            o.z = fmaxf(o.z, 0.0f); o.w = fmaxf(o.w, 0.0f);
        }
        *(float4*)(C + (size_t)row * N + bn + tx * TN) = o;
    }
}

// ---------------------------------------------------------------------------
// 3) GEMM2 with 4-way in-block split-K: out = h @ W2 + b2.
//    32x32 out-tile, 256 threads = 4 k-slices x 64 compute lanes (TM=TN=4).
//    Register double-buffered inner loop; deterministic fixed-order
//    reduction (s0+s1+s2+s3) + bias in epilogue.
// ---------------------------------------------------------------------------
__global__ void __launch_bounds__(256) gemm2_kernel(const float* __restrict__ A,
                                                    const float* __restrict__ B,
                                                    const float* __restrict__ bias,
                                                    float* __restrict__ C) {
    constexpr int K = HIDDEN, N = F_OUT, BM = 32, BN = 32, BK = 16, KP = K / 4;

    __shared__ float As[4][BK][BM + 4];
    __shared__ float Bs[4][BK][BN];
    __shared__ float red[3][BM][BN + 4];

    const int bm   = blockIdx.y * BM;
    const int bn   = blockIdx.x * BN;
    const int tid  = threadIdx.x;
    const int ks   = tid >> 6;           // k-slice 0..3
    const int ctid = tid & 63;
    const int tx   = ctid & 7;           // along N (TN=4)
    const int ty   = ctid >> 3;          // along M (TM=4)

    float acc[4][4] = {};

    const int kbeg = ks * KP;
    for (int k0 = kbeg; k0 < kbeg + KP; k0 += BK) {
        #pragma unroll
        for (int i = 0; i < 2; i++) {    // A slice-tile: 32x16 = 128 float4
            int idx  = ctid + 64 * i;
            int row  = idx >> 2;
            int quad = idx & 3;
            float4 v = *(const float4*)(A + (size_t)(bm + row) * K + k0 + quad * 4);
            As[ks][quad * 4 + 0][row] = v.x;
            As[ks][quad * 4 + 1][row] = v.y;
            As[ks][quad * 4 + 2][row] = v.z;
            As[ks][quad * 4 + 3][row] = v.w;
        }
        #pragma unroll
        for (int i = 0; i < 2; i++) {    // B slice-tile: 16x32 = 128 float4
            int idx  = ctid + 64 * i;
            int row  = idx >> 3;
            int quad = idx & 7;
            *(float4*)&Bs[ks][row][quad * 4] =
                *(const float4*)(B + (size_t)(k0 + row) * N + bn + quad * 4);
        }
        __syncthreads();

        // register double-buffered k-loop
        float4 a4 = *(const float4*)&As[ks][0][ty * 4];
        float4 b4 = *(const float4*)&Bs[ks][0][tx * 4];
        #pragma unroll
        for (int k = 0; k < BK; k++) {
            float4 a4n = a4, b4n = b4;
            if (k + 1 < BK) {
                a4n = *(const float4*)&As[ks][k + 1][ty * 4];
                b4n = *(const float4*)&Bs[ks][k + 1][tx * 4];
            }
            float a[4] = {a4.x, a4.y, a4.z, a4.w};
            float b[4] = {b4.x, b4.y, b4.z, b4.w};
            #pragma unroll
            for (int i = 0; i < 4; i++)
                #pragma unroll
                for (int j = 0; j < 4; j++)
                    acc[i][j] = fmaf(a[i], b[j], acc[i][j]);
            a4 = a4n; b4 = b4n;
        }
        __syncthreads();
    }

    if (ks > 0) {
        #pragma unroll
        for (int i = 0; i < 4; i++)
            #pragma unroll
            for (int j = 0; j < 4; j++)
                red[ks - 1][ty * 4 + i][tx * 4 + j] = acc[i][j];
    }
    __syncthreads();

    if (ks == 0) {
        float4 bv = *(const float4*)(bias + bn + tx * 4);
        #pragma unroll
        for (int i = 0; i < 4; i++) {
            int row = bm + ty * 4 + i;
            float o[4];
            #pragma unroll
            for (int j = 0; j < 4; j++) {
                float s = acc[i][j];
                s += red[0][ty * 4 + i][tx * 4 + j];
                s += red[1][ty * 4 + i][tx * 4 + j];
                s += red[2][ty * 4 + i][tx * 4 + j];
                o[j] = s;
            }
            float4 ov = {o[0] + bv.x, o[1] + bv.y, o[2] + bv.z, o[3] + bv.w};
            *(float4*)(C + (size_t)row * N + bn + tx * 4) = ov;
        }
    }
}

// ---------------------------------------------------------------------------
// Launch. Inputs: x, edge_index, edge_attr, u, batch, W1, b1, W2, b2.
// edge_* unused; int64 inputs arrive as int32 on device.
// ---------------------------------------------------------------------------
extern "C" void kernel_launch(void* const* d_in, const int* in_sizes, int n_in,
                              void* d_out, int out_size) {
    const float* x     = (const float*)d_in[0];
    const float* u     = (const float*)d_in[3];
    const int*   batch = (const int*)d_in[4];
    const float* W1    = (const float*)d_in[5];
    const float* b1    = (const float*)d_in[6];
    const float* W2    = (const float*)d_in[7];
    const float* b2    = (const float*)d_in[8];
    float*       out   = (float*)d_out;

    void *p_concat = nullptr, *p_h = nullptr;
    cudaGetSymbolAddress(&p_concat, g_concat);
    cudaGetSymbolAddress(&p_h, g_h);

    // 1) segment mean + concat (warp-parallel bounds search), single wave
    seg_mean_kernel<<<N_GRAPHS, 256>>>(x, u, batch);

    // 2) h = relu(concat @ W1 + b1): 64x64 tiles, BK=32, grid 128
    gemm_kernel<F_CAT, HIDDEN, 64, 64, 4, 4, 256, true>
        <<<dim3(HIDDEN / 64, N_GRAPHS / 64), 256>>>(
        (const float*)p_concat, W1, b1, (float*)p_h);

    // 3) out = h @ W2 + b2: 32x32 tiles, 4-way in-block split-K, grid 128
    gemm2_kernel<<<dim3(F_OUT / 32, N_GRAPHS / 32), 256>>>(
        (const float*)p_h, W2, b2, out);
}